// round 1
// baseline (speedup 1.0000x reference)
#include <cuda_runtime.h>
#include <math.h>

#define D_MODEL 1024
#define NUM_HEADS 16
#define DK 64
#define BATCH 2
#define SEQ 2048
#define M_TOTAL (BATCH * SEQ)  // 4096
#define RS 68                  // flash smem row stride (floats)

__device__ float g_q[BATCH * NUM_HEADS * SEQ * DK];
__device__ float g_k[BATCH * NUM_HEADS * SEQ * DK];
__device__ float g_v[BATCH * NUM_HEADS * SEQ * DK];
__device__ float g_cat[M_TOTAL * D_MODEL];

// ---------------- projection GEMM ----------------
__global__ __launch_bounds__(256) void proj_gemm_kernel(
    const float* __restrict__ X, const float* __restrict__ W,
    const float* __restrict__ bias, float* __restrict__ out)
{
    __shared__ float As[8][132];
    __shared__ float Bs[8][132];
    const int t  = threadIdx.x;
    const int n0 = blockIdx.x * 128;
    const int m0 = blockIdx.y * 128;
    const int tx = t & 15;
    const int ty = t >> 4;
    const int arow = t >> 1;
    const int ac4  = (t & 1) << 2;
    const int brow = t >> 5;
    const int bc4  = (t & 31) << 2;
    const int bn   = n0 + bc4;
    const float* bptr = W + ((size_t)(bn >> 6) << 16) + (bn & 63);

    float acc[8][8];
#pragma unroll
    for (int i = 0; i < 8; i++)
#pragma unroll
        for (int j = 0; j < 8; j++) acc[i][j] = 0.f;

    for (int k0 = 0; k0 < D_MODEL; k0 += 8) {
        float4 av = *(const float4*)(X + (size_t)(m0 + arow) * D_MODEL + k0 + ac4);
        float4 bv = *(const float4*)(bptr + (size_t)(k0 + brow) * DK);
        __syncthreads();
        As[ac4 + 0][arow] = av.x;
        As[ac4 + 1][arow] = av.y;
        As[ac4 + 2][arow] = av.z;
        As[ac4 + 3][arow] = av.w;
        *(float4*)&Bs[brow][bc4] = bv;
        __syncthreads();
#pragma unroll
        for (int kk = 0; kk < 8; kk++) {
            float a[8], b[8];
            *(float4*)(a)     = *(const float4*)&As[kk][ty * 8];
            *(float4*)(a + 4) = *(const float4*)&As[kk][ty * 8 + 4];
            *(float4*)(b)     = *(const float4*)&Bs[kk][tx * 8];
            *(float4*)(b + 4) = *(const float4*)&Bs[kk][tx * 8 + 4];
#pragma unroll
            for (int i = 0; i < 8; i++)
#pragma unroll
                for (int j = 0; j < 8; j++) acc[i][j] += a[i] * b[j];
        }
    }

#pragma unroll
    for (int i = 0; i < 8; i++) {
        const int m  = m0 + ty * 8 + i;
        const int b_ = m >> 11;
        const int s  = m & 2047;
#pragma unroll
        for (int j4 = 0; j4 < 8; j4 += 4) {
            const int n  = n0 + tx * 8 + j4;
            const int h  = n >> 6;
            const int kd = n & 63;
            float4 r;
            r.x = acc[i][j4 + 0] + bias[n + 0];
            r.y = acc[i][j4 + 1] + bias[n + 1];
            r.z = acc[i][j4 + 2] + bias[n + 2];
            r.w = acc[i][j4 + 3] + bias[n + 3];
            *(float4*)(out + ((((size_t)b_ * NUM_HEADS + h) * SEQ + s) * DK + kd)) = r;
        }
    }
}

// ---------------- flash attention ----------------
__global__ __launch_bounds__(256) void flash_kernel()
{
    extern __shared__ float sm[];
    float* Qs = sm;
    float* Ks = sm + 64 * RS;
    float* Vs = sm + 2 * 64 * RS;
    float* Ss = sm + 3 * 64 * RS;

    const int t  = threadIdx.x;
    const int q0 = blockIdx.x * 64;
    const int bh = blockIdx.y;
    const float* qb = g_q + (size_t)bh * SEQ * DK;
    const float* kb = g_k + (size_t)bh * SEQ * DK;
    const float* vb = g_v + (size_t)bh * SEQ * DK;

#pragma unroll
    for (int rep = 0; rep < 4; rep++) {
        int f = t + rep * 256;
        int row = f >> 4, c4 = (f & 15) << 2;
        *(float4*)&Qs[row * RS + c4] = *(const float4*)&qb[(size_t)(q0 + row) * DK + c4];
    }

    const int tx = t & 15, ty = t >> 4;
    const int srow = t >> 2, sseg = (t & 3) << 4;
    const float scale = 0.125f;

    float m_i = -INFINITY, l_i = 0.f;
    float o[16];
#pragma unroll
    for (int d = 0; d < 16; d++) o[d] = 0.f;

    for (int s0 = 0; s0 < SEQ; s0 += 64) {
        __syncthreads();
#pragma unroll
        for (int rep = 0; rep < 4; rep++) {
            int f = t + rep * 256;
            int row = f >> 4, c4 = (f & 15) << 2;
            *(float4*)&Ks[row * RS + c4] = *(const float4*)&kb[(size_t)(s0 + row) * DK + c4];
            *(float4*)&Vs[row * RS + c4] = *(const float4*)&vb[(size_t)(s0 + row) * DK + c4];
        }
        __syncthreads();

        float acc[4][4];
#pragma unroll
        for (int i = 0; i < 4; i++)
#pragma unroll
            for (int j = 0; j < 4; j++) acc[i][j] = 0.f;

#pragma unroll
        for (int d4 = 0; d4 < 16; d4++) {
            float4 qv[4], kv[4];
#pragma unroll
            for (int i = 0; i < 4; i++) qv[i] = *(const float4*)&Qs[(ty * 4 + i) * RS + d4 * 4];
#pragma unroll
            for (int j = 0; j < 4; j++) kv[j] = *(const float4*)&Ks[(tx * 4 + j) * RS + d4 * 4];
#pragma unroll
            for (int i = 0; i < 4; i++)
#pragma unroll
                for (int j = 0; j < 4; j++)
                    acc[i][j] += qv[i].x * kv[j].x + qv[i].y * kv[j].y
                               + qv[i].z * kv[j].z + qv[i].w * kv[j].w;
        }
#pragma unroll
        for (int i = 0; i < 4; i++)
#pragma unroll
            for (int j = 0; j < 4; j++)
                Ss[(ty * 4 + i) * RS + tx * 4 + j] = acc[i][j] * scale;
        __syncthreads();

        float tmax = -INFINITY;
#pragma unroll
        for (int c = 0; c < 16; c++) tmax = fmaxf(tmax, Ss[srow * RS + sseg + c]);
        tmax = fmaxf(tmax, __shfl_xor_sync(0xffffffffu, tmax, 1));
        tmax = fmaxf(tmax, __shfl_xor_sync(0xffffffffu, tmax, 2));

        float newm = fmaxf(m_i, tmax);
        float alpha = __expf(m_i - newm);
        float psum = 0.f;
#pragma unroll
        for (int c = 0; c < 16; c++) {
            float p = __expf(Ss[srow * RS + sseg + c] - newm);
            Ss[srow * RS + sseg + c] = p;
            psum += p;
        }
        psum += __shfl_xor_sync(0xffffffffu, psum, 1);
        psum += __shfl_xor_sync(0xffffffffu, psum, 2);
        l_i = l_i * alpha + psum;
        m_i = newm;
#pragma unroll
        for (int d = 0; d < 16; d++) o[d] *= alpha;
        __syncthreads();

        for (int j = 0; j < 64; j += 4) {
            float4 p4 = *(const float4*)&Ss[srow * RS + j];
            float pj[4] = {p4.x, p4.y, p4.z, p4.w};
#pragma unroll
            for (int jj = 0; jj < 4; jj++) {
                const float4* vp = (const float4*)&Vs[(j + jj) * RS + sseg];
                float4 v0 = vp[0], v1 = vp[1], v2 = vp[2], v3 = vp[3];
                float p = pj[jj];
                o[0]  += p * v0.x;  o[1]  += p * v0.y;  o[2]  += p * v0.z;  o[3]  += p * v0.w;
                o[4]  += p * v1.x;  o[5]  += p * v1.y;  o[6]  += p * v1.z;  o[7]  += p * v1.w;
                o[8]  += p * v2.x;  o[9]  += p * v2.y;  o[10] += p * v2.z;  o[11] += p * v2.w;
                o[12] += p * v3.x;  o[13] += p * v3.y;  o[14] += p * v3.z;  o[15] += p * v3.w;
            }
        }
    }

    const float inv = 1.f / l_i;
    const int b_ = bh >> 4, h = bh & 15;
    float* op = g_cat + ((size_t)(b_ * SEQ + q0 + srow)) * D_MODEL + h * DK + sseg;
#pragma unroll
    for (int q = 0; q < 4; q++) {
        float4 r;
        r.x = o[q * 4 + 0] * inv;
        r.y = o[q * 4 + 1] * inv;
        r.z = o[q * 4 + 2] * inv;
        r.w = o[q * 4 + 3] * inv;
        ((float4*)op)[q] = r;
    }
}

// ---------------- output projection ----------------
__global__ __launch_bounds__(256) void out_gemm_kernel(
    const float* __restrict__ Wo, const float* __restrict__ bo,
    float* __restrict__ out)
{
    __shared__ float As[8][132];
    __shared__ float Bs[8][132];
    const int t  = threadIdx.x;
    const int n0 = blockIdx.x * 128;
    const int m0 = blockIdx.y * 128;
    const int tx = t & 15;
    const int ty = t >> 4;
    const int arow = t >> 1;
    const int ac4  = (t & 1) << 2;
    const int bnr  = t >> 1;
    const int bk4  = (t & 1) << 2;

    float acc[8][8];
#pragma unroll
    for (int i = 0; i < 8; i++)
#pragma unroll
        for (int j = 0; j < 8; j++) acc[i][j] = 0.f;

    for (int k0 = 0; k0 < D_MODEL; k0 += 8) {
        float4 av = *(const float4*)(g_cat + (size_t)(m0 + arow) * D_MODEL + k0 + ac4);
        float4 wv = *(const float4*)(Wo + (size_t)(n0 + bnr) * D_MODEL + k0 + bk4);
        __syncthreads();
        As[ac4 + 0][arow] = av.x;
        As[ac4 + 1][arow] = av.y;
        As[ac4 + 2][arow] = av.z;
        As[ac4 + 3][arow] = av.w;
        Bs[bk4 + 0][bnr] = wv.x;
        Bs[bk4 + 1][bnr] = wv.y;
        Bs[bk4 + 2][bnr] = wv.z;
        Bs[bk4 + 3][bnr] = wv.w;
        __syncthreads();
#pragma unroll
        for (int kk = 0; kk < 8; kk++) {
            float a[8], b[8];
            *(float4*)(a)     = *(const float4*)&As[kk][ty * 8];
            *(float4*)(a + 4) = *(const float4*)&As[kk][ty * 8 + 4];
            *(float4*)(b)     = *(const float4*)&Bs[kk][tx * 8];
            *(float4*)(b + 4) = *(const float4*)&Bs[kk][tx * 8 + 4];
#pragma unroll
            for (int i = 0; i < 8; i++)
#pragma unroll
                for (int j = 0; j < 8; j++) acc[i][j] += a[i] * b[j];
        }
    }

#pragma unroll
    for (int i = 0; i < 8; i++) {
        const int m = m0 + ty * 8 + i;
#pragma unroll
        for (int j4 = 0; j4 < 8; j4 += 4) {
            const int n = n0 + tx * 8 + j4;
            float4 r;
            r.x = acc[i][j4 + 0] + bo[n + 0];
            r.y = acc[i][j4 + 1] + bo[n + 1];
            r.z = acc[i][j4 + 2] + bo[n + 2];
            r.w = acc[i][j4 + 3] + bo[n + 3];
            *(float4*)(out + (size_t)m * D_MODEL + n) = r;
        }
    }
}

extern "C" void kernel_launch(void* const* d_in, const int* in_sizes, int n_in,
                              void* d_out, int out_size)
{
    const float* Q  = (const float*)d_in[0];
    const float* K  = (const float*)d_in[1];
    const float* V  = (const float*)d_in[2];
    const float* Wq = (const float*)d_in[3];
    const float* bq = (const float*)d_in[4];
    const float* Wk = (const float*)d_in[5];
    const float* bk = (const float*)d_in[6];
    const float* Wv = (const float*)d_in[7];
    const float* bv = (const float*)d_in[8];
    const float* Wo = (const float*)d_in[9];
    const float* bo = (const float*)d_in[10];
    float* out = (float*)d_out;

    float *gq, *gk, *gv;
    cudaGetSymbolAddress((void**)&gq, g_q);
    cudaGetSymbolAddress((void**)&gk, g_k);
    cudaGetSymbolAddress((void**)&gv, g_v);

    const int flash_smem = 4 * 64 * RS * sizeof(float);  // 69632 B
    cudaFuncSetAttribute(flash_kernel, cudaFuncAttributeMaxDynamicSharedMemorySize,
                         flash_smem);

    dim3 gblk(256);
    dim3 ggrd(D_MODEL / 128, M_TOTAL / 128);

    proj_gemm_kernel<<<ggrd, gblk>>>(Q, Wq, bq, gq);
    proj_gemm_kernel<<<ggrd, gblk>>>(K, Wk, bk, gk);
    proj_gemm_kernel<<<ggrd, gblk>>>(V, Wv, bv, gv);

    dim3 fgrd(SEQ / 64, BATCH * NUM_HEADS);
    flash_kernel<<<fgrd, gblk, flash_smem>>>();

    out_gemm_kernel<<<ggrd, gblk>>>(Wo, bo, out);
}

// round 2
// speedup vs baseline: 1.9412x; 1.9412x over previous
#include <cuda_runtime.h>
#include <math.h>
#include <stdint.h>

#define D_MODEL 1024
#define NUM_HEADS 16
#define DK 64
#define BATCH 2
#define SEQ 2048
#define M_TOTAL (BATCH * SEQ)  // 4096
#define RS 68                  // flash smem row stride (floats)

__device__ float g_q[BATCH * NUM_HEADS * SEQ * DK];
__device__ float g_k[BATCH * NUM_HEADS * SEQ * DK];
__device__ float g_v[BATCH * NUM_HEADS * SEQ * DK];
__device__ float g_cat[M_TOTAL * D_MODEL];

__device__ __forceinline__ uint32_t f2tf(float f) {
    uint32_t u;
    asm("cvt.rna.tf32.f32 %0, %1;" : "=r"(u) : "f"(f));
    return u;
}

__device__ __forceinline__ void mma_tf32(float* c, const uint32_t* a, const uint32_t* b) {
    asm volatile(
        "mma.sync.aligned.m16n8k8.row.col.f32.tf32.tf32.f32 "
        "{%0,%1,%2,%3}, {%4,%5,%6,%7}, {%8,%9}, {%0,%1,%2,%3};"
        : "+f"(c[0]), "+f"(c[1]), "+f"(c[2]), "+f"(c[3])
        : "r"(a[0]), "r"(a[1]), "r"(a[2]), "r"(a[3]), "r"(b[0]), "r"(b[1]));
}

// =====================================================================
// TF32 tensor-core GEMM, 128x128 tile, K-chunk 16, double-buffered.
// MODE 0: proj  out[b,h,s,kd] = X[m,:] @ W[h,:,kd] + bias   (W: [H,1024,64])
// MODE 1: out   out[m,n] = X[m,:] @ Wo[n,:]^T + bo          (Wo: [1024,1024])
// A stored [k][m^xor], B stored [k][n^xor], stride 136, xor = ((k>>2)&3)<<2.
// =====================================================================
template <int MODE>
__global__ __launch_bounds__(256) void gemm_tf32_kernel(
    const float* __restrict__ X, const float* __restrict__ W,
    const float* __restrict__ bias, float* __restrict__ out)
{
    __shared__ uint32_t As[2][16 * 136];
    __shared__ uint32_t Bs[2][16 * 136];

    const int t    = threadIdx.x;
    const int n0   = blockIdx.x * 128;
    const int m0   = blockIdx.y * 128;
    const int warp = t >> 5;
    const int lane = t & 31;
    const int gid  = lane >> 2;
    const int tig  = lane & 3;
    const int wm   = (warp & 1) * 64;
    const int wn   = (warp >> 1) * 32;

    float acc[4][4][4];
#pragma unroll
    for (int i = 0; i < 4; i++)
#pragma unroll
        for (int j = 0; j < 4; j++)
#pragma unroll
            for (int k = 0; k < 4; k++) acc[i][j][k] = 0.f;

    float4 ar[2], br[2];

    // ---- staged loaders ----
    auto loadA = [&](int kc) {
#pragma unroll
        for (int rep = 0; rep < 2; rep++) {
            int f = t + rep * 256;
            int m = f >> 2, c4 = (f & 3) << 2;
            ar[rep] = *(const float4*)(X + (size_t)(m0 + m) * D_MODEL + kc * 16 + c4);
        }
    };
    auto storeA = [&](int buf) {
#pragma unroll
        for (int rep = 0; rep < 2; rep++) {
            int f = t + rep * 256;
            int m = f >> 2, c4 = (f & 3) << 2;
            int col = m ^ c4;  // xor const for k in [c4, c4+3]
            As[buf][(c4 + 0) * 136 + col] = f2tf(ar[rep].x);
            As[buf][(c4 + 1) * 136 + col] = f2tf(ar[rep].y);
            As[buf][(c4 + 2) * 136 + col] = f2tf(ar[rep].z);
            As[buf][(c4 + 3) * 136 + col] = f2tf(ar[rep].w);
        }
    };
    auto loadB = [&](int kc) {
#pragma unroll
        for (int rep = 0; rep < 2; rep++) {
            int f = t + rep * 256;
            if (MODE == 0) {
                int k = f >> 5, n4 = (f & 31) << 2;
                int bn = n0 + n4;
                br[rep] = *(const float4*)(W + (size_t)(bn >> 6) * (D_MODEL * DK)
                                             + (size_t)(kc * 16 + k) * DK + (bn & 63));
            } else {
                int n = f >> 2, k4 = (f & 3) << 2;
                br[rep] = *(const float4*)(W + (size_t)(n0 + n) * D_MODEL + kc * 16 + k4);
            }
        }
    };
    auto storeB = [&](int buf) {
#pragma unroll
        for (int rep = 0; rep < 2; rep++) {
            int f = t + rep * 256;
            if (MODE == 0) {
                int k = f >> 5, n4 = (f & 31) << 2;
                int ck = ((k >> 2) & 3) << 2;
                uint32_t* p = &Bs[buf][k * 136 + (n4 ^ ck)];
                p[0] = f2tf(br[rep].x);
                p[1] = f2tf(br[rep].y);
                p[2] = f2tf(br[rep].z);
                p[3] = f2tf(br[rep].w);
            } else {
                int n = f >> 2, k4 = (f & 3) << 2;
                int col = n ^ k4;  // xor const for k in [k4, k4+3]
                Bs[buf][(k4 + 0) * 136 + col] = f2tf(br[rep].x);
                Bs[buf][(k4 + 1) * 136 + col] = f2tf(br[rep].y);
                Bs[buf][(k4 + 2) * 136 + col] = f2tf(br[rep].z);
                Bs[buf][(k4 + 3) * 136 + col] = f2tf(br[rep].w);
            }
        }
    };
    auto compute = [&](int buf) {
#pragma unroll
        for (int ks = 0; ks < 2; ks++) {
            const int kb = ks * 8;
            const int x0 = ks ? 8 : 0;
            const int x1 = ks ? 12 : 4;
            uint32_t af[4][4];
#pragma unroll
            for (int mt = 0; mt < 4; mt++) {
                int mrow = wm + mt * 16 + gid;
                af[mt][0] = As[buf][(kb + tig) * 136 + (mrow ^ x0)];
                af[mt][1] = As[buf][(kb + tig) * 136 + ((mrow + 8) ^ x0)];
                af[mt][2] = As[buf][(kb + tig + 4) * 136 + (mrow ^ x1)];
                af[mt][3] = As[buf][(kb + tig + 4) * 136 + ((mrow + 8) ^ x1)];
            }
            uint32_t bf[4][2];
#pragma unroll
            for (int nt = 0; nt < 4; nt++) {
                int ncol = wn + nt * 8 + gid;
                bf[nt][0] = Bs[buf][(kb + tig) * 136 + (ncol ^ x0)];
                bf[nt][1] = Bs[buf][(kb + tig + 4) * 136 + (ncol ^ x1)];
            }
#pragma unroll
            for (int mt = 0; mt < 4; mt++)
#pragma unroll
                for (int nt = 0; nt < 4; nt++) mma_tf32(acc[mt][nt], af[mt], bf[nt]);
        }
    };

    // ---- pipelined main loop over 64 K-chunks ----
    loadA(0); loadB(0);
    storeA(0); storeB(0);
    __syncthreads();
    int buf = 0;
    for (int kc = 0; kc < 64; kc++) {
        if (kc < 63) { loadA(kc + 1); loadB(kc + 1); }
        compute(buf);
        if (kc < 63) { storeA(buf ^ 1); storeB(buf ^ 1); }
        __syncthreads();
        buf ^= 1;
    }

    // ---- epilogue ----
#pragma unroll
    for (int mt = 0; mt < 4; mt++) {
#pragma unroll
        for (int nt = 0; nt < 4; nt++) {
            const int r0 = m0 + wm + mt * 16 + gid;
            const int r1 = r0 + 8;
            const int c  = n0 + wn + nt * 8 + tig * 2;
            const float bv0 = bias[c], bv1 = bias[c + 1];
            float2 v0 = make_float2(acc[mt][nt][0] + bv0, acc[mt][nt][1] + bv1);
            float2 v1 = make_float2(acc[mt][nt][2] + bv0, acc[mt][nt][3] + bv1);
            if (MODE == 0) {
                const int h = c >> 6, kd = c & 63;
                const int b0_ = r0 >> 11, s0 = r0 & 2047;
                const int b1_ = r1 >> 11, s1 = r1 & 2047;
                *(float2*)(out + (((size_t)b0_ * NUM_HEADS + h) * SEQ + s0) * DK + kd) = v0;
                *(float2*)(out + (((size_t)b1_ * NUM_HEADS + h) * SEQ + s1) * DK + kd) = v1;
            } else {
                *(float2*)(out + (size_t)r0 * D_MODEL + c) = v0;
                *(float2*)(out + (size_t)r1 * D_MODEL + c) = v1;
            }
        }
    }
}

// =====================================================================
// Flash attention v2: 64x64 tiles; S-GEMM and PV both on 16x16 thread
// grid with 4x4 micro-tiles (2x arithmetic intensity in PV vs v1).
// =====================================================================
__global__ __launch_bounds__(256) void flash_kernel()
{
    extern __shared__ float sm[];
    float* Qs = sm;
    float* Ks = sm + 64 * RS;
    float* Vs = sm + 2 * 64 * RS;
    float* Ss = sm + 3 * 64 * RS;
    float* rowAlpha = sm + 4 * 64 * RS;
    float* rowL     = rowAlpha + 64;

    const int t  = threadIdx.x;
    const int q0 = blockIdx.x * 64;
    const int bh = blockIdx.y;
    const float* qb = g_q + (size_t)bh * SEQ * DK;
    const float* kb = g_k + (size_t)bh * SEQ * DK;
    const float* vb = g_v + (size_t)bh * SEQ * DK;

#pragma unroll
    for (int rep = 0; rep < 4; rep++) {
        int f = t + rep * 256;
        int row = f >> 4, c4 = (f & 15) << 2;
        *(float4*)&Qs[row * RS + c4] = *(const float4*)&qb[(size_t)(q0 + row) * DK + c4];
    }

    const int tx = t & 15, ty = t >> 4;      // 4x4 micro-tile mapping
    const int srow = t >> 2, sseg = (t & 3) << 4;  // softmax mapping
    const float scale = 0.125f;

    float m_i = -INFINITY, l_i = 0.f;        // valid in srow mapping
    float o[4][4];
#pragma unroll
    for (int i = 0; i < 4; i++)
#pragma unroll
        for (int j = 0; j < 4; j++) o[i][j] = 0.f;

    for (int s0 = 0; s0 < SEQ; s0 += 64) {
        __syncthreads();
#pragma unroll
        for (int rep = 0; rep < 4; rep++) {
            int f = t + rep * 256;
            int row = f >> 4, c4 = (f & 15) << 2;
            *(float4*)&Ks[row * RS + c4] = *(const float4*)&kb[(size_t)(s0 + row) * DK + c4];
            *(float4*)&Vs[row * RS + c4] = *(const float4*)&vb[(size_t)(s0 + row) * DK + c4];
        }
        __syncthreads();

        // ---- S = Q K^T ----
        float acc[4][4];
#pragma unroll
        for (int i = 0; i < 4; i++)
#pragma unroll
            for (int j = 0; j < 4; j++) acc[i][j] = 0.f;
#pragma unroll
        for (int d4 = 0; d4 < 16; d4++) {
            float4 qv[4], kv[4];
#pragma unroll
            for (int i = 0; i < 4; i++) qv[i] = *(const float4*)&Qs[(ty * 4 + i) * RS + d4 * 4];
#pragma unroll
            for (int j = 0; j < 4; j++) kv[j] = *(const float4*)&Ks[(tx * 4 + j) * RS + d4 * 4];
#pragma unroll
            for (int i = 0; i < 4; i++)
#pragma unroll
                for (int j = 0; j < 4; j++)
                    acc[i][j] += qv[i].x * kv[j].x + qv[i].y * kv[j].y
                               + qv[i].z * kv[j].z + qv[i].w * kv[j].w;
        }
#pragma unroll
        for (int i = 0; i < 4; i++)
#pragma unroll
            for (int j = 0; j < 4; j++)
                Ss[(ty * 4 + i) * RS + tx * 4 + j] = acc[i][j] * scale;
        __syncthreads();

        // ---- online softmax (4 threads per row) ----
        float tmax = -INFINITY;
#pragma unroll
        for (int c = 0; c < 16; c++) tmax = fmaxf(tmax, Ss[srow * RS + sseg + c]);
        tmax = fmaxf(tmax, __shfl_xor_sync(0xffffffffu, tmax, 1));
        tmax = fmaxf(tmax, __shfl_xor_sync(0xffffffffu, tmax, 2));

        float newm = fmaxf(m_i, tmax);
        float alpha = __expf(m_i - newm);
        float psum = 0.f;
#pragma unroll
        for (int c = 0; c < 16; c++) {
            float p = __expf(Ss[srow * RS + sseg + c] - newm);
            Ss[srow * RS + sseg + c] = p;
            psum += p;
        }
        psum += __shfl_xor_sync(0xffffffffu, psum, 1);
        psum += __shfl_xor_sync(0xffffffffu, psum, 2);
        l_i = l_i * alpha + psum;
        m_i = newm;
        if ((t & 3) == 0) rowAlpha[srow] = alpha;
        __syncthreads();

        // ---- O = O*alpha + P @ V (4x4 micro-tile) ----
#pragma unroll
        for (int i = 0; i < 4; i++) {
            float al = rowAlpha[ty * 4 + i];
#pragma unroll
            for (int j = 0; j < 4; j++) o[i][j] *= al;
        }
#pragma unroll
        for (int j4 = 0; j4 < 16; j4++) {
            float4 pv[4], vv[4];
#pragma unroll
            for (int i = 0; i < 4; i++) pv[i] = *(const float4*)&Ss[(ty * 4 + i) * RS + j4 * 4];
#pragma unroll
            for (int jj = 0; jj < 4; jj++) vv[jj] = *(const float4*)&Vs[(j4 * 4 + jj) * RS + tx * 4];
#pragma unroll
            for (int i = 0; i < 4; i++) {
                o[i][0] += pv[i].x * vv[0].x + pv[i].y * vv[1].x + pv[i].z * vv[2].x + pv[i].w * vv[3].x;
                o[i][1] += pv[i].x * vv[0].y + pv[i].y * vv[1].y + pv[i].z * vv[2].y + pv[i].w * vv[3].y;
                o[i][2] += pv[i].x * vv[0].z + pv[i].y * vv[1].z + pv[i].z * vv[2].z + pv[i].w * vv[3].z;
                o[i][3] += pv[i].x * vv[0].w + pv[i].y * vv[1].w + pv[i].z * vv[2].w + pv[i].w * vv[3].w;
            }
        }
    }

    if ((t & 3) == 0) rowL[srow] = l_i;
    __syncthreads();

    const int b_ = bh >> 4, h = bh & 15;
#pragma unroll
    for (int i = 0; i < 4; i++) {
        const float inv = 1.f / rowL[ty * 4 + i];
        float4 r;
        r.x = o[i][0] * inv;
        r.y = o[i][1] * inv;
        r.z = o[i][2] * inv;
        r.w = o[i][3] * inv;
        *(float4*)(g_cat + ((size_t)(b_ * SEQ + q0 + ty * 4 + i)) * D_MODEL + h * DK + tx * 4) = r;
    }
}

extern "C" void kernel_launch(void* const* d_in, const int* in_sizes, int n_in,
                              void* d_out, int out_size)
{
    const float* Q  = (const float*)d_in[0];
    const float* K  = (const float*)d_in[1];
    const float* V  = (const float*)d_in[2];
    const float* Wq = (const float*)d_in[3];
    const float* bq = (const float*)d_in[4];
    const float* Wk = (const float*)d_in[5];
    const float* bk = (const float*)d_in[6];
    const float* Wv = (const float*)d_in[7];
    const float* bv = (const float*)d_in[8];
    const float* Wo = (const float*)d_in[9];
    const float* bo = (const float*)d_in[10];
    float* out = (float*)d_out;

    float *gq, *gk, *gv, *gcat;
    cudaGetSymbolAddress((void**)&gq, g_q);
    cudaGetSymbolAddress((void**)&gk, g_k);
    cudaGetSymbolAddress((void**)&gv, g_v);
    cudaGetSymbolAddress((void**)&gcat, g_cat);

    const int flash_smem = (4 * 64 * RS + 128) * sizeof(float);  // 70144 B
    cudaFuncSetAttribute(flash_kernel, cudaFuncAttributeMaxDynamicSharedMemorySize,
                         flash_smem);

    dim3 gblk(256);
    dim3 ggrd(D_MODEL / 128, M_TOTAL / 128);  // (8, 32)

    gemm_tf32_kernel<0><<<ggrd, gblk>>>(Q, Wq, bq, gq);
    gemm_tf32_kernel<0><<<ggrd, gblk>>>(K, Wk, bk, gk);
    gemm_tf32_kernel<0><<<ggrd, gblk>>>(V, Wv, bv, gv);

    dim3 fgrd(SEQ / 64, BATCH * NUM_HEADS);  // (32, 32)
    flash_kernel<<<fgrd, gblk, flash_smem>>>();

    gemm_tf32_kernel<1><<<ggrd, gblk>>>(gcat, Wo, bo, out);
}

// round 3
// speedup vs baseline: 4.8938x; 2.5211x over previous
#include <cuda_runtime.h>
#include <math.h>
#include <stdint.h>

#define D_MODEL 1024
#define NUM_HEADS 16
#define DK 64
#define BATCH 2
#define SEQ 2048
#define M_TOTAL (BATCH * SEQ)  // 4096
#define RSW 68                 // flash smem row stride (32-bit words)

__device__ float g_q[BATCH * NUM_HEADS * SEQ * DK];
__device__ float g_k[BATCH * NUM_HEADS * SEQ * DK];
__device__ float g_v[BATCH * NUM_HEADS * SEQ * DK];
__device__ float g_cat[M_TOTAL * D_MODEL];

__device__ __forceinline__ uint32_t f2tf(float f) {
    uint32_t u;
    asm("cvt.rna.tf32.f32 %0, %1;" : "=r"(u) : "f"(f));
    return u;
}

__device__ __forceinline__ void mma_tf32(float* c, const uint32_t* a, const uint32_t* b) {
    asm volatile(
        "mma.sync.aligned.m16n8k8.row.col.f32.tf32.tf32.f32 "
        "{%0,%1,%2,%3}, {%4,%5,%6,%7}, {%8,%9}, {%0,%1,%2,%3};"
        : "+f"(c[0]), "+f"(c[1]), "+f"(c[2]), "+f"(c[3])
        : "r"(a[0]), "r"(a[1]), "r"(a[2]), "r"(a[3]), "r"(b[0]), "r"(b[1]));
}

// =====================================================================
// TF32 tensor-core GEMM (unchanged from R2; known-good).
// =====================================================================
template <int MODE>
__global__ __launch_bounds__(256) void gemm_tf32_kernel(
    const float* __restrict__ X, const float* __restrict__ W,
    const float* __restrict__ bias, float* __restrict__ out)
{
    __shared__ uint32_t As[2][16 * 136];
    __shared__ uint32_t Bs[2][16 * 136];

    const int t    = threadIdx.x;
    const int n0   = blockIdx.x * 128;
    const int m0   = blockIdx.y * 128;
    const int warp = t >> 5;
    const int lane = t & 31;
    const int gid  = lane >> 2;
    const int tig  = lane & 3;
    const int wm   = (warp & 1) * 64;
    const int wn   = (warp >> 1) * 32;

    float acc[4][4][4];
#pragma unroll
    for (int i = 0; i < 4; i++)
#pragma unroll
        for (int j = 0; j < 4; j++)
#pragma unroll
            for (int k = 0; k < 4; k++) acc[i][j][k] = 0.f;

    float4 ar[2], br[2];

    auto loadA = [&](int kc) {
#pragma unroll
        for (int rep = 0; rep < 2; rep++) {
            int f = t + rep * 256;
            int m = f >> 2, c4 = (f & 3) << 2;
            ar[rep] = *(const float4*)(X + (size_t)(m0 + m) * D_MODEL + kc * 16 + c4);
        }
    };
    auto storeA = [&](int buf) {
#pragma unroll
        for (int rep = 0; rep < 2; rep++) {
            int f = t + rep * 256;
            int m = f >> 2, c4 = (f & 3) << 2;
            int col = m ^ c4;
            As[buf][(c4 + 0) * 136 + col] = f2tf(ar[rep].x);
            As[buf][(c4 + 1) * 136 + col] = f2tf(ar[rep].y);
            As[buf][(c4 + 2) * 136 + col] = f2tf(ar[rep].z);
            As[buf][(c4 + 3) * 136 + col] = f2tf(ar[rep].w);
        }
    };
    auto loadB = [&](int kc) {
#pragma unroll
        for (int rep = 0; rep < 2; rep++) {
            int f = t + rep * 256;
            if (MODE == 0) {
                int k = f >> 5, n4 = (f & 31) << 2;
                int bn = n0 + n4;
                br[rep] = *(const float4*)(W + (size_t)(bn >> 6) * (D_MODEL * DK)
                                             + (size_t)(kc * 16 + k) * DK + (bn & 63));
            } else {
                int n = f >> 2, k4 = (f & 3) << 2;
                br[rep] = *(const float4*)(W + (size_t)(n0 + n) * D_MODEL + kc * 16 + k4);
            }
        }
    };
    auto storeB = [&](int buf) {
#pragma unroll
        for (int rep = 0; rep < 2; rep++) {
            int f = t + rep * 256;
            if (MODE == 0) {
                int k = f >> 5, n4 = (f & 31) << 2;
                int ck = ((k >> 2) & 3) << 2;
                uint32_t* p = &Bs[buf][k * 136 + (n4 ^ ck)];
                p[0] = f2tf(br[rep].x);
                p[1] = f2tf(br[rep].y);
                p[2] = f2tf(br[rep].z);
                p[3] = f2tf(br[rep].w);
            } else {
                int n = f >> 2, k4 = (f & 3) << 2;
                int col = n ^ k4;
                Bs[buf][(k4 + 0) * 136 + col] = f2tf(br[rep].x);
                Bs[buf][(k4 + 1) * 136 + col] = f2tf(br[rep].y);
                Bs[buf][(k4 + 2) * 136 + col] = f2tf(br[rep].z);
                Bs[buf][(k4 + 3) * 136 + col] = f2tf(br[rep].w);
            }
        }
    };
    auto compute = [&](int buf) {
#pragma unroll
        for (int ks = 0; ks < 2; ks++) {
            const int kb = ks * 8;
            const int x0 = ks ? 8 : 0;
            const int x1 = ks ? 12 : 4;
            uint32_t af[4][4];
#pragma unroll
            for (int mt = 0; mt < 4; mt++) {
                int mrow = wm + mt * 16 + gid;
                af[mt][0] = As[buf][(kb + tig) * 136 + (mrow ^ x0)];
                af[mt][1] = As[buf][(kb + tig) * 136 + ((mrow + 8) ^ x0)];
                af[mt][2] = As[buf][(kb + tig + 4) * 136 + (mrow ^ x1)];
                af[mt][3] = As[buf][(kb + tig + 4) * 136 + ((mrow + 8) ^ x1)];
            }
            uint32_t bf[4][2];
#pragma unroll
            for (int nt = 0; nt < 4; nt++) {
                int ncol = wn + nt * 8 + gid;
                bf[nt][0] = Bs[buf][(kb + tig) * 136 + (ncol ^ x0)];
                bf[nt][1] = Bs[buf][(kb + tig + 4) * 136 + (ncol ^ x1)];
            }
#pragma unroll
            for (int mt = 0; mt < 4; mt++)
#pragma unroll
                for (int nt = 0; nt < 4; nt++) mma_tf32(acc[mt][nt], af[mt], bf[nt]);
        }
    };

    loadA(0); loadB(0);
    storeA(0); storeB(0);
    __syncthreads();
    int buf = 0;
    for (int kc = 0; kc < 64; kc++) {
        if (kc < 63) { loadA(kc + 1); loadB(kc + 1); }
        compute(buf);
        if (kc < 63) { storeA(buf ^ 1); storeB(buf ^ 1); }
        __syncthreads();
        buf ^= 1;
    }

#pragma unroll
    for (int mt = 0; mt < 4; mt++) {
#pragma unroll
        for (int nt = 0; nt < 4; nt++) {
            const int r0 = m0 + wm + mt * 16 + gid;
            const int r1 = r0 + 8;
            const int c  = n0 + wn + nt * 8 + tig * 2;
            const float bv0 = bias[c], bv1 = bias[c + 1];
            float2 v0 = make_float2(acc[mt][nt][0] + bv0, acc[mt][nt][1] + bv1);
            float2 v1 = make_float2(acc[mt][nt][2] + bv0, acc[mt][nt][3] + bv1);
            if (MODE == 0) {
                const int h = c >> 6, kd = c & 63;
                const int b0_ = r0 >> 11, s0 = r0 & 2047;
                const int b1_ = r1 >> 11, s1 = r1 & 2047;
                *(float2*)(out + (((size_t)b0_ * NUM_HEADS + h) * SEQ + s0) * DK + kd) = v0;
                *(float2*)(out + (((size_t)b1_ * NUM_HEADS + h) * SEQ + s1) * DK + kd) = v1;
            } else {
                *(float2*)(out + (size_t)r0 * D_MODEL + c) = v0;
                *(float2*)(out + (size_t)r1 * D_MODEL + c) = v1;
            }
        }
    }
}

// =====================================================================
// Flash attention v3: tf32 mma.sync throughout.
// Block: 256 threads (8 warps), Bq=128 q-rows, Bkv=64. Each warp owns
// 16 q-rows. Q fragments register-resident (scale folded in); K/V smem
// as tf32; fragment-resident online softmax; P via per-warp smem region
// (no block sync on P).
// =====================================================================
__global__ __launch_bounds__(256) void flash_mma_kernel()
{
    extern __shared__ uint32_t smu[];
    uint32_t* Ks = smu;                    // [64][RSW]
    uint32_t* Vs = smu + 64 * RSW;         // [64][RSW]
    uint32_t* Ss = smu + 2 * 64 * RSW;     // [128][RSW] P, per-warp 16-row slices

    const int t    = threadIdx.x;
    const int warp = t >> 5;
    const int lane = t & 31;
    const int gid  = lane >> 2;
    const int tig  = lane & 3;
    const int q0   = blockIdx.x * 128;
    const int bh   = blockIdx.y;

    const float* qb = g_q + (size_t)bh * SEQ * DK;
    const float* kb = g_k + (size_t)bh * SEQ * DK;
    const float* vb = g_v + (size_t)bh * SEQ * DK;

    // Q fragments: rows r0 = q0+warp*16+gid, r1 = r0+8; scale 1/8 folded in.
    const int r0 = q0 + warp * 16 + gid;
    const int r1 = r0 + 8;
    uint32_t qf[8][4];
#pragma unroll
    for (int kk = 0; kk < 8; kk++) {
        qf[kk][0] = f2tf(qb[(size_t)r0 * DK + kk * 8 + tig]     * 0.125f);
        qf[kk][1] = f2tf(qb[(size_t)r1 * DK + kk * 8 + tig]     * 0.125f);
        qf[kk][2] = f2tf(qb[(size_t)r0 * DK + kk * 8 + tig + 4] * 0.125f);
        qf[kk][3] = f2tf(qb[(size_t)r1 * DK + kk * 8 + tig + 4] * 0.125f);
    }

    uint32_t* Sw = Ss + warp * 16 * RSW;   // this warp's private P slice

    float m0 = -INFINITY, m1 = -INFINITY, l0 = 0.f, l1 = 0.f;
    float o[8][4];
#pragma unroll
    for (int j = 0; j < 8; j++)
#pragma unroll
        for (int k = 0; k < 4; k++) o[j][k] = 0.f;

    for (int s0 = 0; s0 < SEQ; s0 += 64) {
        __syncthreads();
        // load K,V tile (64x64) as tf32, vectorized
#pragma unroll
        for (int rep = 0; rep < 4; rep++) {
            int f = t + rep * 256;
            int row = f >> 4, c4 = (f & 15) << 2;
            float4 kv = *(const float4*)&kb[(size_t)(s0 + row) * DK + c4];
            float4 vv = *(const float4*)&vb[(size_t)(s0 + row) * DK + c4];
            uint4 kt = make_uint4(f2tf(kv.x), f2tf(kv.y), f2tf(kv.z), f2tf(kv.w));
            uint4 vt = make_uint4(f2tf(vv.x), f2tf(vv.y), f2tf(vv.z), f2tf(vv.w));
            *(uint4*)&Ks[row * RSW + c4] = kt;
            *(uint4*)&Vs[row * RSW + c4] = vt;
        }
        __syncthreads();

        // ---- S = Q K^T : 8 n-tiles (kv), 8 k-steps (d) ----
        float sacc[8][4];
#pragma unroll
        for (int j = 0; j < 8; j++)
#pragma unroll
            for (int k = 0; k < 4; k++) sacc[j][k] = 0.f;
#pragma unroll
        for (int kk = 0; kk < 8; kk++) {
            uint32_t bf[8][2];
#pragma unroll
            for (int j = 0; j < 8; j++) {
                bf[j][0] = Ks[(j * 8 + gid) * RSW + kk * 8 + tig];
                bf[j][1] = Ks[(j * 8 + gid) * RSW + kk * 8 + tig + 4];
            }
#pragma unroll
            for (int j = 0; j < 8; j++) mma_tf32(sacc[j], qf[kk], bf[j]);
        }

        // ---- fragment-resident online softmax ----
        float t0 = -INFINITY, t1 = -INFINITY;
#pragma unroll
        for (int j = 0; j < 8; j++) {
            t0 = fmaxf(t0, fmaxf(sacc[j][0], sacc[j][1]));
            t1 = fmaxf(t1, fmaxf(sacc[j][2], sacc[j][3]));
        }
        t0 = fmaxf(t0, __shfl_xor_sync(0xffffffffu, t0, 1));
        t0 = fmaxf(t0, __shfl_xor_sync(0xffffffffu, t0, 2));
        t1 = fmaxf(t1, __shfl_xor_sync(0xffffffffu, t1, 1));
        t1 = fmaxf(t1, __shfl_xor_sync(0xffffffffu, t1, 2));

        float nm0 = fmaxf(m0, t0), nm1 = fmaxf(m1, t1);
        float a0 = __expf(m0 - nm0), a1 = __expf(m1 - nm1);
        m0 = nm0; m1 = nm1;

        float p0 = 0.f, p1 = 0.f;
#pragma unroll
        for (int j = 0; j < 8; j++) {
            float e0 = __expf(sacc[j][0] - nm0);
            float e1 = __expf(sacc[j][1] - nm0);
            float e2 = __expf(sacc[j][2] - nm1);
            float e3 = __expf(sacc[j][3] - nm1);
            p0 += e0 + e1;
            p1 += e2 + e3;
            // P -> per-warp smem slice as tf32 (cols 8j+2tig, +1)
            uint2 w0 = make_uint2(f2tf(e0), f2tf(e1));
            uint2 w1 = make_uint2(f2tf(e2), f2tf(e3));
            *(uint2*)&Sw[gid * RSW + j * 8 + tig * 2]       = w0;
            *(uint2*)&Sw[(gid + 8) * RSW + j * 8 + tig * 2] = w1;
        }
        p0 += __shfl_xor_sync(0xffffffffu, p0, 1);
        p0 += __shfl_xor_sync(0xffffffffu, p0, 2);
        p1 += __shfl_xor_sync(0xffffffffu, p1, 1);
        p1 += __shfl_xor_sync(0xffffffffu, p1, 2);
        l0 = l0 * a0 + p0;
        l1 = l1 * a1 + p1;

#pragma unroll
        for (int j = 0; j < 8; j++) {
            o[j][0] *= a0; o[j][1] *= a0;
            o[j][2] *= a1; o[j][3] *= a1;
        }
        __syncwarp();

        // ---- O += P V : 8 n-tiles (d), 8 k-steps (kv) ----
#pragma unroll
        for (int kk = 0; kk < 8; kk++) {
            uint32_t af[4];
            af[0] = Sw[gid * RSW + kk * 8 + tig];
            af[1] = Sw[(gid + 8) * RSW + kk * 8 + tig];
            af[2] = Sw[gid * RSW + kk * 8 + tig + 4];
            af[3] = Sw[(gid + 8) * RSW + kk * 8 + tig + 4];
#pragma unroll
            for (int j = 0; j < 8; j++) {
                uint32_t bf[2];
                bf[0] = Vs[(kk * 8 + tig) * RSW + j * 8 + gid];
                bf[1] = Vs[(kk * 8 + tig + 4) * RSW + j * 8 + gid];
                mma_tf32(o[j], af, bf);
            }
        }
        __syncwarp();   // Sw reads done before next iteration's writes
    }

    // ---- epilogue: normalize, write concat layout ----
    const float i0 = 1.f / l0, i1 = 1.f / l1;
    const int b_ = bh >> 4, h = bh & 15;
    float* row0 = g_cat + (size_t)(b_ * SEQ + r0) * D_MODEL + h * DK;
    float* row1 = g_cat + (size_t)(b_ * SEQ + r1) * D_MODEL + h * DK;
#pragma unroll
    for (int j = 0; j < 8; j++) {
        *(float2*)(row0 + j * 8 + tig * 2) = make_float2(o[j][0] * i0, o[j][1] * i0);
        *(float2*)(row1 + j * 8 + tig * 2) = make_float2(o[j][2] * i1, o[j][3] * i1);
    }
}

extern "C" void kernel_launch(void* const* d_in, const int* in_sizes, int n_in,
                              void* d_out, int out_size)
{
    const float* Q  = (const float*)d_in[0];
    const float* K  = (const float*)d_in[1];
    const float* V  = (const float*)d_in[2];
    const float* Wq = (const float*)d_in[3];
    const float* bq = (const float*)d_in[4];
    const float* Wk = (const float*)d_in[5];
    const float* bk = (const float*)d_in[6];
    const float* Wv = (const float*)d_in[7];
    const float* bv = (const float*)d_in[8];
    const float* Wo = (const float*)d_in[9];
    const float* bo = (const float*)d_in[10];
    float* out = (float*)d_out;

    float *gq, *gk, *gv, *gcat;
    cudaGetSymbolAddress((void**)&gq, g_q);
    cudaGetSymbolAddress((void**)&gk, g_k);
    cudaGetSymbolAddress((void**)&gv, g_v);
    cudaGetSymbolAddress((void**)&gcat, g_cat);

    const int flash_smem = (64 + 64 + 128) * RSW * sizeof(uint32_t);  // 69632 B
    cudaFuncSetAttribute(flash_mma_kernel, cudaFuncAttributeMaxDynamicSharedMemorySize,
                         flash_smem);

    dim3 gblk(256);
    dim3 ggrd(D_MODEL / 128, M_TOTAL / 128);  // (8, 32)

    gemm_tf32_kernel<0><<<ggrd, gblk>>>(Q, Wq, bq, gq);
    gemm_tf32_kernel<0><<<ggrd, gblk>>>(K, Wk, bk, gk);
    gemm_tf32_kernel<0><<<ggrd, gblk>>>(V, Wv, bv, gv);

    dim3 fgrd(SEQ / 128, BATCH * NUM_HEADS);  // (16, 32)
    flash_mma_kernel<<<fgrd, gblk, flash_smem>>>();

    gemm_tf32_kernel<1><<<ggrd, gblk>>>(gcat, Wo, bo, out);
}